// round 1
// baseline (speedup 1.0000x reference)
#include <cuda_runtime.h>
#include <math.h>

// Shapes (fixed by the problem):
//   x : [8, 512, 64, 64] f32   (B*C = 4096 planes of 64x64)
//   w1: [32, 512], b1: [32], w2: [512, 32], b2: [512]
// out: [8, 512, 64, 64] f32

#define NPLANES 4096
#define PLANE_ELEMS 4096   // 64*64
#define HW 64

// Scratch (no allocations allowed -> device globals)
__device__ float g_gap[NPLANES];
__device__ int   g_q[NPLANES];
__device__ float g_fb[NPLANES];

// ---------------------------------------------------------------------------
// Kernel 1: per-plane mean (adaptive_avg_pool2d to 1x1)
// ---------------------------------------------------------------------------
__global__ __launch_bounds__(256) void gap_kernel(const float* __restrict__ x) {
    const int plane = blockIdx.x;
    const float4* __restrict__ p =
        reinterpret_cast<const float4*>(x + (size_t)plane * PLANE_ELEMS);

    float sum = 0.f;
    #pragma unroll 4
    for (int i = threadIdx.x; i < PLANE_ELEMS / 4; i += 256) {
        float4 v = p[i];
        sum += (v.x + v.y) + (v.z + v.w);
    }
    // warp reduce
    #pragma unroll
    for (int off = 16; off > 0; off >>= 1)
        sum += __shfl_down_sync(0xffffffffu, sum, off);

    __shared__ float warp_sums[8];
    const int lane = threadIdx.x & 31, wid = threadIdx.x >> 5;
    if (lane == 0) warp_sums[wid] = sum;
    __syncthreads();
    if (threadIdx.x == 0) {
        float t = 0.f;
        #pragma unroll
        for (int i = 0; i < 8; i++) t += warp_sums[i];
        g_gap[plane] = t * (1.0f / (float)PLANE_ELEMS);
    }
}

// ---------------------------------------------------------------------------
// Kernel 2: SE bottleneck + routing. One block per batch image.
//   hmid = relu(gap @ w1^T + b1)   [8,32]
//   s    = relu(hmid @ w2^T + b2)  [8,512]
//   q    = clip(floor(s), 0, 5); frac_b = s - q  (frac_s = 1 - frac_b)
// ---------------------------------------------------------------------------
__global__ __launch_bounds__(512) void se_kernel(const float* __restrict__ w1,
                                                 const float* __restrict__ b1,
                                                 const float* __restrict__ w2,
                                                 const float* __restrict__ b2) {
    __shared__ float sgap[512];
    __shared__ float shmid[32];
    const int b = blockIdx.x;
    const int t = threadIdx.x;

    sgap[t] = g_gap[b * 512 + t];
    __syncthreads();

    if (t < 32) {
        float acc = b1[t];
        const float* wr = w1 + t * 512;
        #pragma unroll 8
        for (int k = 0; k < 512; k++) acc = fmaf(sgap[k], wr[k], acc);
        shmid[t] = fmaxf(acc, 0.f);
    }
    __syncthreads();

    float acc = b2[t];
    const float* wr = w2 + t * 32;
    #pragma unroll
    for (int j = 0; j < 32; j++) acc = fmaf(shmid[j], wr[j], acc);
    const float s = fmaxf(acc, 0.f);

    int q = (int)floorf(s);
    q = min(max(q, 0), 5);
    const int plane = b * 512 + t;
    g_q[plane]  = q;
    g_fb[plane] = s - (float)q;   // frac_s = 1 - frac_b (q_b - q_s == 1 always)
}

// ---------------------------------------------------------------------------
// Kernel 3: dual separable SAME max-pool + blend + residual.
// One block per (b,c) plane; r = q is uniform within the block.
//   rowS[x] = max over clamped [x-r,   x+r]      (row pass, radius r)
//   rowB[x] = rowS[x] extended by t[x-r-1], t[x+r+1]   (radius r+1, +2 reads)
//   poolS   = col-max of rowS over [y-r,   y+r]
//   poolB   = col-max of rowB over [y-r-1, y+r+1]
//   out     = fb*poolB + fs*poolS + x
// Clamped ranges == SAME padding with -inf (max ignores padding).
// ---------------------------------------------------------------------------
__global__ __launch_bounds__(256) void pool_kernel(const float* __restrict__ x,
                                                   float* __restrict__ out) {
    __shared__ float tile[PLANE_ELEMS];
    __shared__ float rowS[PLANE_ELEMS];
    __shared__ float rowB[PLANE_ELEMS];

    const int plane = blockIdx.x;
    const size_t base = (size_t)plane * PLANE_ELEMS;

    // load plane (vectorized, coalesced)
    {
        const float4* __restrict__ src = reinterpret_cast<const float4*>(x + base);
        float4* dst = reinterpret_cast<float4*>(tile);
        #pragma unroll 4
        for (int i = threadIdx.x; i < PLANE_ELEMS / 4; i += 256) dst[i] = src[i];
    }
    const int   r  = g_q[plane];        // block-uniform
    const float fb = g_fb[plane];
    const float fs = 1.0f - fb;
    __syncthreads();

    // ---- row pass: rowS (radius r) and rowB (radius r+1) in one sweep ----
    #pragma unroll 2
    for (int i = threadIdx.x; i < PLANE_ELEMS; i += 256) {
        const int y = i >> 6, xq = i & 63;
        const float* rowp = tile + (y << 6);
        int a = xq - r; if (a < 0) a = 0;
        int e = xq + r; if (e > HW - 1) e = HW - 1;
        float m = rowp[a];
        for (int xx = a + 1; xx <= e; ++xx) m = fmaxf(m, rowp[xx]);
        rowS[i] = m;
        float mb = m;
        if (xq - r - 1 >= 0)      mb = fmaxf(mb, rowp[xq - r - 1]);
        if (xq + r + 1 <= HW - 1) mb = fmaxf(mb, rowp[xq + r + 1]);
        rowB[i] = mb;
    }
    __syncthreads();

    // ---- column pass + blend + residual + store ----
    #pragma unroll 2
    for (int i = threadIdx.x; i < PLANE_ELEMS; i += 256) {
        const int y = i >> 6, xq = i & 63;

        int a = y - r; if (a < 0) a = 0;
        int e = y + r; if (e > HW - 1) e = HW - 1;
        float ms = rowS[(a << 6) + xq];
        for (int yy = a + 1; yy <= e; ++yy) ms = fmaxf(ms, rowS[(yy << 6) + xq]);

        int ab = y - r - 1; if (ab < 0) ab = 0;
        int eb = y + r + 1; if (eb > HW - 1) eb = HW - 1;
        float mb = rowB[(ab << 6) + xq];
        for (int yy = ab + 1; yy <= eb; ++yy) mb = fmaxf(mb, rowB[(yy << 6) + xq]);

        out[base + i] = fmaf(fb, mb, fmaf(fs, ms, tile[i]));
    }
}

// ---------------------------------------------------------------------------
extern "C" void kernel_launch(void* const* d_in, const int* in_sizes, int n_in,
                              void* d_out, int out_size) {
    const float* x  = (const float*)d_in[0];
    const float* w1 = (const float*)d_in[1];
    const float* b1 = (const float*)d_in[2];
    const float* w2 = (const float*)d_in[3];
    const float* b2 = (const float*)d_in[4];
    float* out = (float*)d_out;

    gap_kernel<<<NPLANES, 256>>>(x);
    se_kernel<<<8, 512>>>(w1, b1, w2, b2);
    pool_kernel<<<NPLANES, 256>>>(x, out);
}

// round 2
// speedup vs baseline: 1.2365x; 1.2365x over previous
#include <cuda_runtime.h>
#include <math.h>
#include <float.h>

// Shapes (fixed): x [8,512,64,64] f32; w1 [32,512]; b1 [32]; w2 [512,32]; b2 [512]
#define NPLANES 4096
#define PLANE_ELEMS 4096
#define HW 64
#define NEG_INF (-FLT_MAX)

// padded tile: 64 rows, stride 80, data cols [8,72)
#define TSTR 80
#define TOFF 8
// padded row-max arrays: 76 rows (6 pad top/bottom), stride 64, data rows [6,70)
#define RSTR 64
#define ROFF 6

#define SM_TILE  (64 * TSTR)         // 5120 floats
#define SM_ROW   (76 * RSTR)         // 4864 floats
#define SMEM_FLOATS (SM_TILE + 2 * SM_ROW)   // 14848 floats = 59392 B

// Scratch (no allocations allowed -> device globals)
__device__ float g_gap[NPLANES];
__device__ int   g_q[NPLANES];
__device__ float g_fb[NPLANES];

// ---------------------------------------------------------------------------
// Kernel 1: per-plane mean
// ---------------------------------------------------------------------------
__global__ __launch_bounds__(256) void gap_kernel(const float* __restrict__ x) {
    const int plane = blockIdx.x;
    const float4* __restrict__ p =
        reinterpret_cast<const float4*>(x + (size_t)plane * PLANE_ELEMS);

    float sum = 0.f;
    #pragma unroll 4
    for (int i = threadIdx.x; i < PLANE_ELEMS / 4; i += 256) {
        float4 v = p[i];
        sum += (v.x + v.y) + (v.z + v.w);
    }
    #pragma unroll
    for (int off = 16; off > 0; off >>= 1)
        sum += __shfl_down_sync(0xffffffffu, sum, off);

    __shared__ float warp_sums[8];
    const int lane = threadIdx.x & 31, wid = threadIdx.x >> 5;
    if (lane == 0) warp_sums[wid] = sum;
    __syncthreads();
    if (threadIdx.x == 0) {
        float t = 0.f;
        #pragma unroll
        for (int i = 0; i < 8; i++) t += warp_sums[i];
        g_gap[plane] = t * (1.0f / (float)PLANE_ELEMS);
    }
}

// ---------------------------------------------------------------------------
// Kernel 2: SE bottleneck + routing (one block per batch image)
// ---------------------------------------------------------------------------
__global__ __launch_bounds__(512) void se_kernel(const float* __restrict__ w1,
                                                 const float* __restrict__ b1,
                                                 const float* __restrict__ w2,
                                                 const float* __restrict__ b2) {
    __shared__ float sgap[512];
    __shared__ float shmid[32];
    const int b = blockIdx.x;
    const int t = threadIdx.x;

    sgap[t] = g_gap[b * 512 + t];
    __syncthreads();

    if (t < 32) {
        float acc = b1[t];
        const float* wr = w1 + t * 512;
        #pragma unroll 8
        for (int k = 0; k < 512; k++) acc = fmaf(sgap[k], wr[k], acc);
        shmid[t] = fmaxf(acc, 0.f);
    }
    __syncthreads();

    float acc = b2[t];
    const float* wr = w2 + t * 32;
    #pragma unroll
    for (int j = 0; j < 32; j++) acc = fmaf(shmid[j], wr[j], acc);
    const float s = fmaxf(acc, 0.f);

    int q = (int)floorf(s);
    q = min(max(q, 0), 5);
    const int plane = b * 512 + t;
    g_q[plane]  = q;
    g_fb[plane] = s - (float)q;   // frac_s = 1 - frac_b
}

// ---------------------------------------------------------------------------
// Balanced-tree max over N elements at given stride (compile-time N)
// ---------------------------------------------------------------------------
template<int N>
__device__ __forceinline__ float vmax(const float* __restrict__ p, int stride) {
    if constexpr (N == 1) {
        return p[0];
    } else {
        constexpr int H = N / 2;
        return fmaxf(vmax<H>(p, stride), vmax<N - H>(p + H * stride, stride));
    }
}

// ---------------------------------------------------------------------------
// Templated plane processor: all window loops fully unrolled, no clamping
// (padding with -FLT_MAX replicates SAME max-pool semantics exactly).
// ---------------------------------------------------------------------------
template<int R>
__device__ __forceinline__ void process_plane(
    const float* __restrict__ xg, float* __restrict__ outg,
    float* __restrict__ tile, float* __restrict__ rowS, float* __restrict__ rowB,
    float fb)
{
    const int t = threadIdx.x;
    const float fs = 1.0f - fb;

    // ---- fill pads ----
    // tile horizontal pads: cols [0,8) and [72,80) of each of 64 rows -> 1024
    #pragma unroll
    for (int i = t; i < 64 * 16; i += 256) {
        const int y = i >> 4, c = i & 15;
        const int col = (c < 8) ? c : (64 + c);   // 0..7 or 72..79
        tile[y * TSTR + col] = NEG_INF;
    }
    // rowS/rowB vertical pads: rows [0,6) and [70,76), 64 cols each -> 768 per array
    #pragma unroll
    for (int i = t; i < 12 * 64; i += 256) {
        const int pr = i >> 6;                    // 0..11
        const int row = (pr < 6) ? pr : (pr + 64);  // 0..5 or 70..75
        const int col = i & 63;
        rowS[row * RSTR + col] = NEG_INF;
        rowB[row * RSTR + col] = NEG_INF;
    }

    // ---- load plane (vectorized; (y*80+8)*4 bytes is 16B aligned) ----
    {
        const float4* __restrict__ src = reinterpret_cast<const float4*>(xg);
        #pragma unroll
        for (int i = t; i < PLANE_ELEMS / 4; i += 256) {
            const int y = i >> 4, x4 = (i & 15) << 2;
            *reinterpret_cast<float4*>(tile + y * TSTR + TOFF + x4) = src[i];
        }
    }
    __syncthreads();

    // ---- row pass: radius R (S) and R+1 (B = S window + 2 edge samples) ----
    #pragma unroll 4
    for (int k = 0; k < 16; k++) {
        const int i = t + (k << 8);
        const int y = i >> 6, x = i & 63;
        const float* p = tile + y * TSTR + TOFF + x;
        const float mS = vmax<2 * R + 1>(p - R, 1);
        const float mB = fmaxf(mS, fmaxf(p[-R - 1], p[R + 1]));
        rowS[(y + ROFF) * RSTR + x] = mS;
        rowB[(y + ROFF) * RSTR + x] = mB;
    }
    __syncthreads();

    // ---- column pass + blend + residual ----
    #pragma unroll 4
    for (int k = 0; k < 16; k++) {
        const int i = t + (k << 8);
        const int y = i >> 6, x = i & 63;
        const int base = (y + ROFF) * RSTR + x;
        const float ms = vmax<2 * R + 1>(rowS + base - R * RSTR, RSTR);
        const float mb = vmax<2 * R + 3>(rowB + base - (R + 1) * RSTR, RSTR);
        const float resid = tile[y * TSTR + TOFF + x];
        outg[i] = fmaf(fb, mb, fmaf(fs, ms, resid));
    }
}

// ---------------------------------------------------------------------------
// Kernel 3: one block per plane; r is block-uniform -> switch dispatch
// ---------------------------------------------------------------------------
__global__ __launch_bounds__(256) void pool_kernel(const float* __restrict__ x,
                                                   float* __restrict__ out) {
    extern __shared__ float smem[];
    float* tile = smem;
    float* rowS = smem + SM_TILE;
    float* rowB = rowS + SM_ROW;

    const int plane = blockIdx.x;
    const size_t base = (size_t)plane * PLANE_ELEMS;
    const int r = g_q[plane];
    const float fb = g_fb[plane];
    const float* xg = x + base;
    float* outg = out + base;

    switch (r) {
        case 0: process_plane<0>(xg, outg, tile, rowS, rowB, fb); break;
        case 1: process_plane<1>(xg, outg, tile, rowS, rowB, fb); break;
        case 2: process_plane<2>(xg, outg, tile, rowS, rowB, fb); break;
        case 3: process_plane<3>(xg, outg, tile, rowS, rowB, fb); break;
        case 4: process_plane<4>(xg, outg, tile, rowS, rowB, fb); break;
        default: process_plane<5>(xg, outg, tile, rowS, rowB, fb); break;
    }
}

// ---------------------------------------------------------------------------
extern "C" void kernel_launch(void* const* d_in, const int* in_sizes, int n_in,
                              void* d_out, int out_size) {
    const float* x  = (const float*)d_in[0];
    const float* w1 = (const float*)d_in[1];
    const float* b1 = (const float*)d_in[2];
    const float* w2 = (const float*)d_in[3];
    const float* b2 = (const float*)d_in[4];
    float* out = (float*)d_out;

    const int smem_bytes = SMEM_FLOATS * (int)sizeof(float);
    cudaFuncSetAttribute(pool_kernel,
                         cudaFuncAttributeMaxDynamicSharedMemorySize, smem_bytes);

    gap_kernel<<<NPLANES, 256>>>(x);
    se_kernel<<<8, 512>>>(w1, b1, w2, b2);
    pool_kernel<<<NPLANES, 256, smem_bytes>>>(x, out);
}

// round 3
// speedup vs baseline: 1.5501x; 1.2536x over previous
#include <cuda_runtime.h>
#include <math.h>
#include <float.h>

// Shapes (fixed): x [8,512,64,64] f32; w1 [32,512]; b1 [32]; w2 [512,32]; b2 [512]
#define NPLANES 4096
#define PLANE_ELEMS 4096
#define HW 64
#define NEG_INF (-FLT_MAX)

// padded tile: 64 rows, stride 80 floats, data cols [8,72)
#define TSTR 80
#define TOFF 8
// padded row-max arrays: 76 rows (6 pad top/bottom), stride 64
#define RSTR 64
#define ROFF 6

#define SM_TILE  (64 * TSTR)                 // 5120 floats
#define SM_ROW   (76 * RSTR)                 // 4864 floats
#define SMEM_FLOATS (SM_TILE + 2 * SM_ROW)   // 14848 floats = 59392 B

#define POOL_GRID 444                        // 148 SMs * 3 CTAs

// Scratch (no allocations allowed -> device globals)
__device__ float g_gap[NPLANES];
__device__ int   g_q[NPLANES];
__device__ float g_fb[NPLANES];

// ---------------------------------------------------------------------------
// Kernel 1: per-plane mean (DRAM-bound; also warms L2 with x for pool pass)
// ---------------------------------------------------------------------------
__global__ __launch_bounds__(256) void gap_kernel(const float* __restrict__ x) {
    const int plane = blockIdx.x;
    const float4* __restrict__ p =
        reinterpret_cast<const float4*>(x + (size_t)plane * PLANE_ELEMS);

    float sum = 0.f;
    #pragma unroll 4
    for (int i = threadIdx.x; i < PLANE_ELEMS / 4; i += 256) {
        float4 v = p[i];
        sum += (v.x + v.y) + (v.z + v.w);
    }
    #pragma unroll
    for (int off = 16; off > 0; off >>= 1)
        sum += __shfl_down_sync(0xffffffffu, sum, off);

    __shared__ float warp_sums[8];
    const int lane = threadIdx.x & 31, wid = threadIdx.x >> 5;
    if (lane == 0) warp_sums[wid] = sum;
    __syncthreads();
    if (threadIdx.x == 0) {
        float t = 0.f;
        #pragma unroll
        for (int i = 0; i < 8; i++) t += warp_sums[i];
        g_gap[plane] = t * (1.0f / (float)PLANE_ELEMS);
    }
}

// ---------------------------------------------------------------------------
// Kernel 2: SE bottleneck + routing (one block per batch image)
// ---------------------------------------------------------------------------
__global__ __launch_bounds__(512) void se_kernel(const float* __restrict__ w1,
                                                 const float* __restrict__ b1,
                                                 const float* __restrict__ w2,
                                                 const float* __restrict__ b2) {
    __shared__ float sgap[512];
    __shared__ float shmid[32];
    const int b = blockIdx.x;
    const int t = threadIdx.x;

    sgap[t] = g_gap[b * 512 + t];
    __syncthreads();

    if (t < 32) {
        float acc = b1[t];
        const float* wr = w1 + t * 512;
        #pragma unroll 8
        for (int k = 0; k < 512; k++) acc = fmaf(sgap[k], wr[k], acc);
        shmid[t] = fmaxf(acc, 0.f);
    }
    __syncthreads();

    float acc = b2[t];
    const float* wr = w2 + t * 32;
    #pragma unroll
    for (int j = 0; j < 32; j++) acc = fmaf(shmid[j], wr[j], acc);
    const float s = fmaxf(acc, 0.f);

    int q = (int)floorf(s);
    q = min(max(q, 0), 5);
    const int plane = b * 512 + t;
    g_q[plane]  = q;
    g_fb[plane] = s - (float)q;   // frac_s = 1 - frac_b
}

// ---------------------------------------------------------------------------
__device__ __forceinline__ float4 fmax4(float4 a, float4 b) {
    return make_float4(fmaxf(a.x, b.x), fmaxf(a.y, b.y),
                       fmaxf(a.z, b.z), fmaxf(a.w, b.w));
}
__device__ __forceinline__ float4 ld4s(const float* p) {
    return *reinterpret_cast<const float4*>(p);
}

// 4 sliding maxes of window W over float4 rows in smem at stride RSTR floats.
// out[j] = componentwise max over rows base[(j)..(j+W-1)]. Streaming: only
// head(3) + running core + tail(3) live -> low register pressure.
template<int W>
__device__ __forceinline__ void colslide(const float* __restrict__ base,
                                         float4 out[4]) {
    if constexpr (W == 1) {
        #pragma unroll
        for (int j = 0; j < 4; j++) out[j] = ld4s(base + j * RSTR);
    } else if constexpr (W <= 3) {
        float4 a[W + 3];
        #pragma unroll
        for (int k = 0; k < W + 3; k++) a[k] = ld4s(base + k * RSTR);
        #pragma unroll
        for (int j = 0; j < 4; j++) {
            float4 m = a[j];
            #pragma unroll
            for (int u = 1; u < W; u++) m = fmax4(m, a[j + u]);
            out[j] = m;
        }
    } else {
        float4 a0 = ld4s(base), a1 = ld4s(base + RSTR), a2 = ld4s(base + 2 * RSTR);
        float4 core = ld4s(base + 3 * RSTR);
        #pragma unroll
        for (int k = 4; k < W; k++) core = fmax4(core, ld4s(base + k * RSTR));
        float4 aW  = ld4s(base + W * RSTR);
        float4 aW1 = ld4s(base + (W + 1) * RSTR);
        float4 aW2 = ld4s(base + (W + 2) * RSTR);
        out[0] = fmax4(fmax4(core, a0), fmax4(a1, a2));
        out[1] = fmax4(fmax4(core, a1), fmax4(a2, aW));
        out[2] = fmax4(fmax4(core, a2), fmax4(aW, aW1));
        out[3] = fmax4(fmax4(core, aW), fmax4(aW1, aW2));
    }
}

// ---------------------------------------------------------------------------
// Templated plane processor. Pads (NEG_INF) pre-filled by caller.
// ---------------------------------------------------------------------------
template<int R>
__device__ __forceinline__ void process_plane(
    const float* __restrict__ xg, float* __restrict__ outg,
    float* __restrict__ tile, float* __restrict__ rowS, float* __restrict__ rowB,
    float fb)
{
    const int t = threadIdx.x;
    const float fs = 1.0f - fb;

    // ---- load plane ----
    {
        const float4* __restrict__ src = reinterpret_cast<const float4*>(xg);
        #pragma unroll
        for (int k = 0; k < 4; k++) {
            const int i = t + (k << 8);
            const int y = i >> 4, x4 = (i & 15) << 2;
            *reinterpret_cast<float4*>(tile + y * TSTR + TOFF + x4) = src[i];
        }
    }
    __syncthreads();

    // ---- row pass: 4-wide outputs, 5x LDS.128 covers radius R+1 <= 6 ----
    #pragma unroll
    for (int k = 0; k < 4; k++) {
        const int item = t + (k << 8);
        const int y = item >> 4, c = item & 15;
        // r[i] = tile float at logical col (4c - 8 + i); smem idx y*80 + 4c + i
        const float* tb = tile + y * TSTR + (c << 2);
        float r[20];
        #pragma unroll
        for (int u = 0; u < 5; u++)
            *reinterpret_cast<float4*>(&r[4 * u]) = ld4s(tb + 4 * u);

        float mS[4], mB[4];
        if constexpr (R == 0) {
            #pragma unroll
            for (int j = 0; j < 4; j++) mS[j] = r[8 + j];
        } else if constexpr (R == 1) {
            #pragma unroll
            for (int j = 0; j < 4; j++)
                mS[j] = fmaxf(r[7 + j], fmaxf(r[8 + j], r[9 + j]));
        } else {
            float core = r[11 - R];
            #pragma unroll
            for (int u = 12 - R; u <= 8 + R; u++) core = fmaxf(core, r[u]);
            mS[0] = fmaxf(fmaxf(core, r[8 - R]),  fmaxf(r[9 - R],  r[10 - R]));
            mS[1] = fmaxf(fmaxf(core, r[9 - R]),  fmaxf(r[10 - R], r[9 + R]));
            mS[2] = fmaxf(fmaxf(core, r[10 - R]), fmaxf(r[9 + R],  r[10 + R]));
            mS[3] = fmaxf(fmaxf(core, r[9 + R]),  fmaxf(r[10 + R], r[11 + R]));
        }
        #pragma unroll
        for (int j = 0; j < 4; j++)
            mB[j] = fmaxf(mS[j], fmaxf(r[7 - R + j], r[9 + R + j]));

        const int ro = (y + ROFF) * RSTR + (c << 2);
        *reinterpret_cast<float4*>(rowS + ro) = make_float4(mS[0], mS[1], mS[2], mS[3]);
        *reinterpret_cast<float4*>(rowB + ro) = make_float4(mB[0], mB[1], mB[2], mB[3]);
    }
    __syncthreads();

    // ---- column pass (4 wide x 4 tall per thread) + blend + residual ----
    {
        const int c = t & 15, y0 = (t >> 4) << 2;
        float4 mS4[4], mB4[4];
        colslide<2 * R + 1>(rowS + (y0 - R + ROFF) * RSTR + (c << 2), mS4);
        colslide<2 * R + 3>(rowB + (y0 - R - 1 + ROFF) * RSTR + (c << 2), mB4);
        #pragma unroll
        for (int j = 0; j < 4; j++) {
            const float4 res = ld4s(tile + (y0 + j) * TSTR + TOFF + (c << 2));
            float4 o;
            o.x = fmaf(fb, mB4[j].x, fmaf(fs, mS4[j].x, res.x));
            o.y = fmaf(fb, mB4[j].y, fmaf(fs, mS4[j].y, res.y));
            o.z = fmaf(fb, mB4[j].z, fmaf(fs, mS4[j].z, res.z));
            o.w = fmaf(fb, mB4[j].w, fmaf(fs, mS4[j].w, res.w));
            *reinterpret_cast<float4*>(outg + (y0 + j) * HW + (c << 2)) = o;
        }
    }
}

// ---------------------------------------------------------------------------
// Kernel 3: persistent; pads filled once; grid-stride over planes
// ---------------------------------------------------------------------------
__global__ __launch_bounds__(256, 3) void pool_kernel(const float* __restrict__ x,
                                                      float* __restrict__ out) {
    extern __shared__ float smem[];
    float* tile = smem;
    float* rowS = smem + SM_TILE;
    float* rowB = rowS + SM_ROW;

    // fill constant -inf pads once
    for (int i = threadIdx.x; i < 64 * 16; i += 256) {
        const int y = i >> 4, c = i & 15;
        const int col = (c < 8) ? c : (64 + c);     // 0..7 or 72..79
        tile[y * TSTR + col] = NEG_INF;
    }
    for (int i = threadIdx.x; i < 12 * 64; i += 256) {
        const int pr = i >> 6;
        const int row = (pr < 6) ? pr : (pr + 64);  // 0..5 or 70..75
        const int col = i & 63;
        rowS[row * RSTR + col] = NEG_INF;
        rowB[row * RSTR + col] = NEG_INF;
    }
    // (visibility ordered by the __syncthreads inside process_plane)

    for (int plane = blockIdx.x; plane < NPLANES; plane += gridDim.x) {
        const size_t base = (size_t)plane * PLANE_ELEMS;
        const int r = g_q[plane];
        const float fb = g_fb[plane];
        const float* xg = x + base;
        float* outg = out + base;

        switch (r) {
            case 0: process_plane<0>(xg, outg, tile, rowS, rowB, fb); break;
            case 1: process_plane<1>(xg, outg, tile, rowS, rowB, fb); break;
            case 2: process_plane<2>(xg, outg, tile, rowS, rowB, fb); break;
            case 3: process_plane<3>(xg, outg, tile, rowS, rowB, fb); break;
            case 4: process_plane<4>(xg, outg, tile, rowS, rowB, fb); break;
            default: process_plane<5>(xg, outg, tile, rowS, rowB, fb); break;
        }
        __syncthreads();   // protect tile/rowS/rowB before next plane overwrite
    }
}

// ---------------------------------------------------------------------------
extern "C" void kernel_launch(void* const* d_in, const int* in_sizes, int n_in,
                              void* d_out, int out_size) {
    const float* x  = (const float*)d_in[0];
    const float* w1 = (const float*)d_in[1];
    const float* b1 = (const float*)d_in[2];
    const float* w2 = (const float*)d_in[3];
    const float* b2 = (const float*)d_in[4];
    float* out = (float*)d_out;

    const int smem_bytes = SMEM_FLOATS * (int)sizeof(float);
    cudaFuncSetAttribute(pool_kernel,
                         cudaFuncAttributeMaxDynamicSharedMemorySize, smem_bytes);

    gap_kernel<<<NPLANES, 256>>>(x);
    se_kernel<<<8, 512>>>(w1, b1, w2, b2);
    pool_kernel<<<POOL_GRID, 256, smem_bytes>>>(x, out);
}